// round 1
// baseline (speedup 1.0000x reference)
#include <cuda_runtime.h>
#include <cuda_bf16.h>
#include <math.h>

// ---------------------------------------------------------------------------
// Problem constants (fixed shapes from setup_inputs)
// ---------------------------------------------------------------------------
#define NODES0 200000
#define NODES1 100000
#define NODES2 50000
#define NODES3 25000
#define FIN    256
#define DH     64
#define NHEAD  3
#define COUT   40
#define FMID   (NHEAD * DH)   // 192

// ---------------------------------------------------------------------------
// Static device scratch (no allocation allowed)
// ---------------------------------------------------------------------------
__device__ __align__(128) float g_hbuf[(size_t)NODES0 * FMID];   // projected features (largest: 200000x192)
__device__ __align__(128) float g_obuf[(size_t)NODES1 * FMID];   // layer outputs (largest: 100000x192)
__device__ __align__(128) float g_el[(size_t)NODES0 * NHEAD];
__device__ __align__(128) float g_er[(size_t)NODES0 * NHEAD];
__device__ int g_rowptr[NODES1 + 1];

// ---------------------------------------------------------------------------
// SGEMM: C[M,N] = A[M,K] @ B[K,N], fp32, row-major.
// BM=128, BN=64, BK=16, 256 threads, 8x4 microtile.
// Requires: K % 16 == 0, N % 4 == 0 (true here: K in {256,192}, N in {192,40})
// ---------------------------------------------------------------------------
__global__ __launch_bounds__(256) void sgemm_kernel(
    const float* __restrict__ A, const float* __restrict__ B,
    float* __restrict__ C, int M, int N, int K)
{
    constexpr int BM = 128, BN = 64, BK = 16, TM = 8, TN = 4;
    __shared__ float As[BK][BM];
    __shared__ float Bs[BK][BN];

    const int tid  = threadIdx.x;
    const int brow = blockIdx.y * BM;
    const int bcol = blockIdx.x * BN;
    const int tx = tid % (BN / TN);   // 0..15
    const int ty = tid / (BN / TN);   // 0..15

    float acc[TM][TN];
#pragma unroll
    for (int i = 0; i < TM; i++)
#pragma unroll
        for (int j = 0; j < TN; j++) acc[i][j] = 0.f;

    for (int k0 = 0; k0 < K; k0 += BK) {
        // Load A tile: 128x16 floats = 512 float4, 256 threads -> 2 each
#pragma unroll
        for (int i = 0; i < 2; i++) {
            int idx = tid + i * 256;          // float4 index
            int r   = idx / (BK / 4);         // 0..127
            int c4  = idx % (BK / 4);         // 0..3
            float4 v = make_float4(0.f, 0.f, 0.f, 0.f);
            int grow = brow + r;
            if (grow < M)
                v = *(const float4*)&A[(size_t)grow * K + k0 + c4 * 4];
            As[c4 * 4 + 0][r] = v.x;
            As[c4 * 4 + 1][r] = v.y;
            As[c4 * 4 + 2][r] = v.z;
            As[c4 * 4 + 3][r] = v.w;
        }
        // Load B tile: 16x64 floats = 256 float4, 1 per thread
        {
            int r  = tid / (BN / 4);          // 0..15
            int c4 = tid % (BN / 4);          // 0..15
            float4 v = make_float4(0.f, 0.f, 0.f, 0.f);
            int gcol = bcol + c4 * 4;
            if (gcol < N)
                v = *(const float4*)&B[(size_t)(k0 + r) * N + gcol];
            Bs[r][c4 * 4 + 0] = v.x;
            Bs[r][c4 * 4 + 1] = v.y;
            Bs[r][c4 * 4 + 2] = v.z;
            Bs[r][c4 * 4 + 3] = v.w;
        }
        __syncthreads();

#pragma unroll
        for (int k = 0; k < BK; k++) {
            float a[TM], b[TN];
#pragma unroll
            for (int i = 0; i < TM; i++) a[i] = As[k][ty * TM + i];
#pragma unroll
            for (int j = 0; j < TN; j++) b[j] = Bs[k][tx * TN + j];
#pragma unroll
            for (int i = 0; i < TM; i++)
#pragma unroll
                for (int j = 0; j < TN; j++)
                    acc[i][j] = fmaf(a[i], b[j], acc[i][j]);
        }
        __syncthreads();
    }

#pragma unroll
    for (int i = 0; i < TM; i++) {
        int row = brow + ty * TM + i;
        if (row >= M) continue;
#pragma unroll
        for (int j = 0; j < TN; j++) {
            int col = bcol + tx * TN + j;
            if (col < N) C[(size_t)row * N + col] = acc[i][j];
        }
    }
}

// ---------------------------------------------------------------------------
// Per-node attention logits: el[n,h] = sum_d h[n,h,d]*al[h,d]; er likewise.
// One warp per (node, head).
// ---------------------------------------------------------------------------
__global__ void elr_kernel(const float* __restrict__ h,
                           const float* __restrict__ al,
                           const float* __restrict__ ar,
                           float* __restrict__ el, float* __restrict__ er,
                           int Nn, int H, int D)
{
    int gw   = (blockIdx.x * blockDim.x + threadIdx.x) >> 5;
    int lane = threadIdx.x & 31;
    if (gw >= Nn * H) return;
    int n = gw / H, head = gw % H;
    const float* hp  = h  + (size_t)n * H * D + head * D;
    const float* alp = al + head * D;
    const float* arp = ar + head * D;
    float sl = 0.f, sr = 0.f;
    for (int d = lane; d < D; d += 32) {
        float v = hp[d];
        sl = fmaf(v, alp[d], sl);
        sr = fmaf(v, arp[d], sr);
    }
#pragma unroll
    for (int o = 16; o; o >>= 1) {
        sl += __shfl_xor_sync(0xffffffffu, sl, o);
        sr += __shfl_xor_sync(0xffffffffu, sr, o);
    }
    if (lane == 0) {
        el[n * H + head] = sl;
        er[n * H + head] = sr;
    }
}

// ---------------------------------------------------------------------------
// row_ptr from sorted dst: rp[d] = lower_bound(dst, d). One thread per d.
// ---------------------------------------------------------------------------
__global__ void rowptr_kernel(const int* __restrict__ dst, int E, int n_dst,
                              int* __restrict__ rp)
{
    int d = blockIdx.x * blockDim.x + threadIdx.x;
    if (d > n_dst) return;
    int lo = 0, hi = E;
    while (lo < hi) {
        int mid = (lo + hi) >> 1;
        if (dst[mid] < d) lo = mid + 1; else hi = mid;
    }
    rp[d] = lo;
}

// ---------------------------------------------------------------------------
// Per-destination softmax aggregation. One block per dst node.
// Block = max(H*D, 64) threads. Warps [0,H) compute max & sum for head w.
// Then each thread t < H*D accumulates one output feature over edges.
// ---------------------------------------------------------------------------
__device__ __forceinline__ float leaky02(float v) {
    return v > 0.f ? v : 0.2f * v;
}

template <int H, int D, bool RELU>
__global__ void aggregate_kernel(const float* __restrict__ h,
                                 const float* __restrict__ el,
                                 const float* __restrict__ er,
                                 const int* __restrict__ src,
                                 const int* __restrict__ rp,
                                 float* __restrict__ out)
{
    const int d = blockIdx.x;
    const int start = rp[d];
    const int end   = rp[d + 1];

    __shared__ float sh_m[H];
    __shared__ float sh_is[H];

    const int warp = threadIdx.x >> 5;
    const int lane = threadIdx.x & 31;

    if (warp < H) {
        const float er_d = er[d * H + warp];
        float mx = -INFINITY;
        for (int e = start + lane; e < end; e += 32) {
            float v = leaky02(el[src[e] * H + warp] + er_d);
            mx = fmaxf(mx, v);
        }
#pragma unroll
        for (int o = 16; o; o >>= 1)
            mx = fmaxf(mx, __shfl_xor_sync(0xffffffffu, mx, o));
        float s = 0.f;
        for (int e = start + lane; e < end; e += 32) {
            float v = leaky02(el[src[e] * H + warp] + er_d);
            s += __expf(v - mx);
        }
#pragma unroll
        for (int o = 16; o; o >>= 1)
            s += __shfl_xor_sync(0xffffffffu, s, o);
        if (lane == 0) {
            sh_m[warp]  = mx;
            sh_is[warp] = (end > start) ? 1.0f / s : 0.f;
        }
    }
    __syncthreads();

    const int t = threadIdx.x;
    if (t < H * D) {
        const int head = t / D;
        const float m    = sh_m[head];
        const float is   = sh_is[head];
        const float er_d = er[d * H + head];
        float acc = 0.f;
        for (int e = start; e < end; e++) {
            int sn = src[e];
            float v = leaky02(el[sn * H + head] + er_d);
            float alpha = __expf(v - m) * is;
            acc = fmaf(h[(size_t)sn * (H * D) + t], alpha, acc);
        }
        if (RELU) acc = fmaxf(acc, 0.f);
        out[(size_t)d * (H * D) + t] = acc;
    }
}

// ---------------------------------------------------------------------------
// Launch
// ---------------------------------------------------------------------------
static inline int ceil_div(int a, int b) { return (a + b - 1) / b; }

extern "C" void kernel_launch(void* const* d_in, const int* in_sizes, int n_in,
                              void* d_out, int out_size)
{
    const float* x    = (const float*)d_in[0];
    const int*   src0 = (const int*)  d_in[1];
    const int*   dst0 = (const int*)  d_in[2];
    const int*   src1 = (const int*)  d_in[3];
    const int*   dst1 = (const int*)  d_in[4];
    const int*   src2 = (const int*)  d_in[5];
    const int*   dst2 = (const int*)  d_in[6];
    const float* W0   = (const float*)d_in[7];
    const float* al0  = (const float*)d_in[8];
    const float* ar0  = (const float*)d_in[9];
    const float* W1   = (const float*)d_in[10];
    const float* al1  = (const float*)d_in[11];
    const float* ar1  = (const float*)d_in[12];
    const float* W2   = (const float*)d_in[13];
    const float* al2  = (const float*)d_in[14];
    const float* ar2  = (const float*)d_in[15];
    float* out = (float*)d_out;

    const int E0 = in_sizes[1];
    const int E1 = in_sizes[3];
    const int E2 = in_sizes[5];

    float *hbuf, *obuf, *el, *er;
    int* rp;
    cudaGetSymbolAddress((void**)&hbuf, g_hbuf);
    cudaGetSymbolAddress((void**)&obuf, g_obuf);
    cudaGetSymbolAddress((void**)&el,   g_el);
    cudaGetSymbolAddress((void**)&er,   g_er);
    cudaGetSymbolAddress((void**)&rp,   g_rowptr);

    // ---------------- Layer 0: 200000x256 @ 256x192 ----------------
    {
        dim3 grid(ceil_div(FMID, 64), ceil_div(NODES0, 128));
        sgemm_kernel<<<grid, 256>>>(x, W0, hbuf, NODES0, FMID, FIN);

        int warps = NODES0 * NHEAD;
        elr_kernel<<<ceil_div(warps * 32, 256), 256>>>(hbuf, al0, ar0, el, er,
                                                       NODES0, NHEAD, DH);
        rowptr_kernel<<<ceil_div(NODES1 + 1, 256), 256>>>(dst0, E0, NODES1, rp);
        aggregate_kernel<NHEAD, DH, true><<<NODES1, FMID>>>(hbuf, el, er, src0, rp, obuf);
    }

    // ---------------- Layer 1: 100000x192 @ 192x192 ----------------
    {
        dim3 grid(ceil_div(FMID, 64), ceil_div(NODES1, 128));
        sgemm_kernel<<<grid, 256>>>(obuf, W1, hbuf, NODES1, FMID, FMID);

        int warps = NODES1 * NHEAD;
        elr_kernel<<<ceil_div(warps * 32, 256), 256>>>(hbuf, al1, ar1, el, er,
                                                       NODES1, NHEAD, DH);
        rowptr_kernel<<<ceil_div(NODES2 + 1, 256), 256>>>(dst1, E1, NODES2, rp);
        aggregate_kernel<NHEAD, DH, true><<<NODES2, FMID>>>(hbuf, el, er, src1, rp, obuf);
    }

    // ---------------- Layer 2: 50000x192 @ 192x40 (H=1, D=40) ----------------
    {
        dim3 grid(ceil_div(COUT, 64), ceil_div(NODES2, 128));
        sgemm_kernel<<<grid, 256>>>(obuf, W2, hbuf, NODES2, COUT, FMID);

        int warps = NODES2 * 1;
        elr_kernel<<<ceil_div(warps * 32, 256), 256>>>(hbuf, al2, ar2, el, er,
                                                       NODES2, 1, COUT);
        rowptr_kernel<<<ceil_div(NODES3 + 1, 256), 256>>>(dst2, E2, NODES3, rp);
        aggregate_kernel<1, COUT, false><<<NODES3, 64>>>(hbuf, el, er, src2, rp, out);
    }
}

// round 2
// speedup vs baseline: 1.2602x; 1.2602x over previous
#include <cuda_runtime.h>
#include <cuda_bf16.h>
#include <mma.h>
#include <math.h>

using namespace nvcuda;

// ---------------------------------------------------------------------------
// Problem constants (fixed shapes from setup_inputs)
// ---------------------------------------------------------------------------
#define NODES0 200000
#define NODES1 100000
#define NODES2 50000
#define NODES3 25000
#define FIN    256
#define DH     64
#define NHEAD  3
#define COUT   40
#define FMID   (NHEAD * DH)   // 192

// ---------------------------------------------------------------------------
// Static device scratch (no allocation allowed)
// ---------------------------------------------------------------------------
__device__ __align__(128) float g_hbuf[(size_t)NODES0 * FMID];
__device__ __align__(128) float g_obuf[(size_t)NODES1 * FMID];
__device__ __align__(128) float g_el[(size_t)NODES0 * NHEAD];
__device__ __align__(128) float g_er[(size_t)NODES0 * NHEAD];
__device__ int g_rowptr[NODES1 + 1];

// ---------------------------------------------------------------------------
// TF32 tensor-core GEMM: C[M,N] = A[M,K] @ B[K,N], row-major fp32 in/out.
// BM=128, BN=64, BK=16; 8 warps in 4x2 layout; warp tile 32x32 = 2x2 wmma frags.
// Requires: K % 16 == 0, N % 64 == 0 within launched grid cols, M % 16 == 0.
// ---------------------------------------------------------------------------
__global__ __launch_bounds__(256) void gemm_tf32_kernel(
    const float* __restrict__ A, const float* __restrict__ B,
    float* __restrict__ C, int M, int N, int K)
{
    constexpr int BM = 128, BN = 64, BK = 16;
    constexpr int LDA = BK + 4;   // 20 (mult of 4, rows 16B-aligned)
    constexpr int LDB = BN + 4;   // 68

    __shared__ float As[BM * LDA];
    __shared__ float Bs[BK * LDB];

    const int tid  = threadIdx.x;
    const int warp = tid >> 5;
    const int wm   = warp >> 1;   // 0..3
    const int wn   = warp & 1;    // 0..1
    const int brow = blockIdx.y * BM;
    const int bcol = blockIdx.x * BN;

    wmma::fragment<wmma::accumulator, 16, 16, 8, float> c[2][2];
#pragma unroll
    for (int i = 0; i < 2; i++)
#pragma unroll
        for (int j = 0; j < 2; j++) wmma::fill_fragment(c[i][j], 0.0f);

    for (int k0 = 0; k0 < K; k0 += BK) {
        // A tile: 128x16 = 512 float4, 256 threads x 2
#pragma unroll
        for (int i = 0; i < 2; i++) {
            int idx = tid + i * 256;
            int r   = idx >> 2;       // 0..127
            int c4  = idx & 3;        // 0..3
            float4 v = make_float4(0.f, 0.f, 0.f, 0.f);
            int grow = brow + r;
            if (grow < M)
                v = *(const float4*)&A[(size_t)grow * K + k0 + c4 * 4];
            float* dst = &As[r * LDA + c4 * 4];
            dst[0] = wmma::__float_to_tf32(v.x);
            dst[1] = wmma::__float_to_tf32(v.y);
            dst[2] = wmma::__float_to_tf32(v.z);
            dst[3] = wmma::__float_to_tf32(v.w);
        }
        // B tile: 16x64 = 256 float4, 1 per thread
        {
            int r  = tid >> 4;        // 0..15
            int c4 = tid & 15;        // 0..15
            float4 v = make_float4(0.f, 0.f, 0.f, 0.f);
            int gcol = bcol + c4 * 4;
            if (gcol + 3 < N)
                v = *(const float4*)&B[(size_t)(k0 + r) * N + gcol];
            float* dst = &Bs[r * LDB + c4 * 4];
            dst[0] = wmma::__float_to_tf32(v.x);
            dst[1] = wmma::__float_to_tf32(v.y);
            dst[2] = wmma::__float_to_tf32(v.z);
            dst[3] = wmma::__float_to_tf32(v.w);
        }
        __syncthreads();

#pragma unroll
        for (int kk = 0; kk < BK; kk += 8) {
            wmma::fragment<wmma::matrix_a, 16, 16, 8, wmma::precision::tf32, wmma::row_major> a[2];
            wmma::fragment<wmma::matrix_b, 16, 16, 8, wmma::precision::tf32, wmma::row_major> b[2];
#pragma unroll
            for (int i = 0; i < 2; i++)
                wmma::load_matrix_sync(a[i], &As[(wm * 32 + i * 16) * LDA + kk], LDA);
#pragma unroll
            for (int j = 0; j < 2; j++)
                wmma::load_matrix_sync(b[j], &Bs[kk * LDB + wn * 32 + j * 16], LDB);
#pragma unroll
            for (int i = 0; i < 2; i++)
#pragma unroll
                for (int j = 0; j < 2; j++)
                    wmma::mma_sync(c[i][j], a[i], b[j], c[i][j]);
        }
        __syncthreads();
    }

    // Store (M % 16 == 0 guarantees no partial fragments at the M edge)
#pragma unroll
    for (int i = 0; i < 2; i++) {
        int row0 = brow + wm * 32 + i * 16;
        if (row0 + 16 > M) continue;
#pragma unroll
        for (int j = 0; j < 2; j++) {
            int col0 = bcol + wn * 32 + j * 16;
            wmma::store_matrix_sync(&C[(size_t)row0 * N + col0], c[i][j], N,
                                    wmma::mem_row_major);
        }
    }
}

// ---------------------------------------------------------------------------
// fp32 SIMT SGEMM (layer-2 only: N=40). BM=128,BN=64,BK=16, 8x4 microtile.
// ---------------------------------------------------------------------------
__global__ __launch_bounds__(256) void sgemm_kernel(
    const float* __restrict__ A, const float* __restrict__ B,
    float* __restrict__ C, int M, int N, int K)
{
    constexpr int BM = 128, BN = 64, BK = 16, TM = 8, TN = 4;
    __shared__ float As[BK][BM];
    __shared__ float Bs[BK][BN];

    const int tid  = threadIdx.x;
    const int brow = blockIdx.y * BM;
    const int bcol = blockIdx.x * BN;
    const int tx = tid % (BN / TN);
    const int ty = tid / (BN / TN);

    float acc[TM][TN];
#pragma unroll
    for (int i = 0; i < TM; i++)
#pragma unroll
        for (int j = 0; j < TN; j++) acc[i][j] = 0.f;

    for (int k0 = 0; k0 < K; k0 += BK) {
#pragma unroll
        for (int i = 0; i < 2; i++) {
            int idx = tid + i * 256;
            int r   = idx / (BK / 4);
            int c4  = idx % (BK / 4);
            float4 v = make_float4(0.f, 0.f, 0.f, 0.f);
            int grow = brow + r;
            if (grow < M)
                v = *(const float4*)&A[(size_t)grow * K + k0 + c4 * 4];
            As[c4 * 4 + 0][r] = v.x;
            As[c4 * 4 + 1][r] = v.y;
            As[c4 * 4 + 2][r] = v.z;
            As[c4 * 4 + 3][r] = v.w;
        }
        {
            int r  = tid / (BN / 4);
            int c4 = tid % (BN / 4);
            float4 v = make_float4(0.f, 0.f, 0.f, 0.f);
            int gcol = bcol + c4 * 4;
            if (gcol + 3 < N)
                v = *(const float4*)&B[(size_t)(k0 + r) * N + gcol];
            Bs[r][c4 * 4 + 0] = v.x;
            Bs[r][c4 * 4 + 1] = v.y;
            Bs[r][c4 * 4 + 2] = v.z;
            Bs[r][c4 * 4 + 3] = v.w;
        }
        __syncthreads();

#pragma unroll
        for (int k = 0; k < BK; k++) {
            float a[TM], b[TN];
#pragma unroll
            for (int i = 0; i < TM; i++) a[i] = As[k][ty * TM + i];
#pragma unroll
            for (int j = 0; j < TN; j++) b[j] = Bs[k][tx * TN + j];
#pragma unroll
            for (int i = 0; i < TM; i++)
#pragma unroll
                for (int j = 0; j < TN; j++)
                    acc[i][j] = fmaf(a[i], b[j], acc[i][j]);
        }
        __syncthreads();
    }

#pragma unroll
    for (int i = 0; i < TM; i++) {
        int row = brow + ty * TM + i;
        if (row >= M) continue;
#pragma unroll
        for (int j = 0; j < TN; j++) {
            int col = bcol + tx * TN + j;
            if (col < N) C[(size_t)row * N + col] = acc[i][j];
        }
    }
}

// ---------------------------------------------------------------------------
// Per-node attention logits.
// ---------------------------------------------------------------------------
__global__ void elr_kernel(const float* __restrict__ h,
                           const float* __restrict__ al,
                           const float* __restrict__ ar,
                           float* __restrict__ el, float* __restrict__ er,
                           int Nn, int H, int D)
{
    int gw   = (blockIdx.x * blockDim.x + threadIdx.x) >> 5;
    int lane = threadIdx.x & 31;
    if (gw >= Nn * H) return;
    int n = gw / H, head = gw % H;
    const float* hp  = h  + (size_t)n * H * D + head * D;
    const float* alp = al + head * D;
    const float* arp = ar + head * D;
    float sl = 0.f, sr = 0.f;
    for (int d = lane; d < D; d += 32) {
        float v = hp[d];
        sl = fmaf(v, alp[d], sl);
        sr = fmaf(v, arp[d], sr);
    }
#pragma unroll
    for (int o = 16; o; o >>= 1) {
        sl += __shfl_xor_sync(0xffffffffu, sl, o);
        sr += __shfl_xor_sync(0xffffffffu, sr, o);
    }
    if (lane == 0) {
        el[n * H + head] = sl;
        er[n * H + head] = sr;
    }
}

// ---------------------------------------------------------------------------
// row_ptr from sorted dst.
// ---------------------------------------------------------------------------
__global__ void rowptr_kernel(const int* __restrict__ dst, int E, int n_dst,
                              int* __restrict__ rp)
{
    int d = blockIdx.x * blockDim.x + threadIdx.x;
    if (d > n_dst) return;
    int lo = 0, hi = E;
    while (lo < hi) {
        int mid = (lo + hi) >> 1;
        if (dst[mid] < d) lo = mid + 1; else hi = mid;
    }
    rp[d] = lo;
}

// ---------------------------------------------------------------------------
// Aggregate v2: one block per dst node.
// Phase A: warps [0,H) compute per-head max & 1/sum of exp.
// Phase B: per-edge alpha computed ONCE into smem (chunked), then features
//          accumulated as float4 with SLOTS edge-slots in flight.
// blockDim = SLOTS * (H*D/4).
// ---------------------------------------------------------------------------
__device__ __forceinline__ float leaky02(float v) {
    return v > 0.f ? v : 0.2f * v;
}

template <int H, int D, int SLOTS, bool RELU>
__global__ void aggregate2_kernel(const float* __restrict__ h,
                                  const float* __restrict__ el,
                                  const float* __restrict__ er,
                                  const int* __restrict__ src,
                                  const int* __restrict__ rp,
                                  float* __restrict__ out)
{
    constexpr int HD  = H * D;
    constexpr int HD4 = HD / 4;
    constexpr int CH  = 64;          // edge chunk

    const int d = blockIdx.x;
    const int start = rp[d];
    const int end   = rp[d + 1];

    __shared__ float sh_m[H], sh_is[H], sh_er[H];
    __shared__ int   sh_src[CH];
    __shared__ float sh_alpha[CH][H];
    __shared__ float4 red[SLOTS * HD4];

    const int tid  = threadIdx.x;
    const int warp = tid >> 5;
    const int lane = tid & 31;

    // ---- Phase A: per-head max & sum ----
    if (warp < H) {
        const float er_d = er[d * H + warp];
        float mx = -INFINITY;
        for (int e = start + lane; e < end; e += 32)
            mx = fmaxf(mx, leaky02(el[src[e] * H + warp] + er_d));
#pragma unroll
        for (int o = 16; o; o >>= 1)
            mx = fmaxf(mx, __shfl_xor_sync(0xffffffffu, mx, o));
        float s = 0.f;
        for (int e = start + lane; e < end; e += 32)
            s += __expf(leaky02(el[src[e] * H + warp] + er_d) - mx);
#pragma unroll
        for (int o = 16; o; o >>= 1)
            s += __shfl_xor_sync(0xffffffffu, s, o);
        if (lane == 0) {
            sh_m[warp]  = mx;
            sh_is[warp] = (end > start) ? 1.0f / s : 0.f;
            sh_er[warp] = er_d;
        }
    }
    __syncthreads();

    // ---- Phase B: chunked alpha + float4 accumulation ----
    const int slot = tid / HD4;      // 0..SLOTS-1
    const int j    = tid % HD4;      // float4 feature index
    const int head = (j * 4) / D;

    float4 acc = make_float4(0.f, 0.f, 0.f, 0.f);

    for (int c0 = start; c0 < end; c0 += CH) {
        const int cnt = min(CH, end - c0);
        if (tid < cnt) {
            int sn = src[c0 + tid];
            sh_src[tid] = sn;
#pragma unroll
            for (int hh = 0; hh < H; hh++) {
                float v = leaky02(el[sn * H + hh] + sh_er[hh]);
                sh_alpha[tid][hh] = __expf(v - sh_m[hh]) * sh_is[hh];
            }
        }
        __syncthreads();

        for (int e = slot; e < cnt; e += SLOTS) {
            const int   sn = sh_src[e];
            const float a  = sh_alpha[e][head];
            const float4 v = ((const float4*)(h + (size_t)sn * HD))[j];
            acc.x = fmaf(v.x, a, acc.x);
            acc.y = fmaf(v.y, a, acc.y);
            acc.z = fmaf(v.z, a, acc.z);
            acc.w = fmaf(v.w, a, acc.w);
        }
        __syncthreads();
    }

    // ---- Reduce SLOTS partials and write ----
    red[tid] = acc;
    __syncthreads();
    if (slot == 0) {
        float4 r = red[j];
#pragma unroll
        for (int s = 1; s < SLOTS; s++) {
            float4 o = red[s * HD4 + j];
            r.x += o.x; r.y += o.y; r.z += o.z; r.w += o.w;
        }
        if (RELU) {
            r.x = fmaxf(r.x, 0.f); r.y = fmaxf(r.y, 0.f);
            r.z = fmaxf(r.z, 0.f); r.w = fmaxf(r.w, 0.f);
        }
        ((float4*)(out + (size_t)d * HD))[j] = r;
    }
}

// ---------------------------------------------------------------------------
// Launch
// ---------------------------------------------------------------------------
static inline int ceil_div(int a, int b) { return (a + b - 1) / b; }

extern "C" void kernel_launch(void* const* d_in, const int* in_sizes, int n_in,
                              void* d_out, int out_size)
{
    const float* x    = (const float*)d_in[0];
    const int*   src0 = (const int*)  d_in[1];
    const int*   dst0 = (const int*)  d_in[2];
    const int*   src1 = (const int*)  d_in[3];
    const int*   dst1 = (const int*)  d_in[4];
    const int*   src2 = (const int*)  d_in[5];
    const int*   dst2 = (const int*)  d_in[6];
    const float* W0   = (const float*)d_in[7];
    const float* al0  = (const float*)d_in[8];
    const float* ar0  = (const float*)d_in[9];
    const float* W1   = (const float*)d_in[10];
    const float* al1  = (const float*)d_in[11];
    const float* ar1  = (const float*)d_in[12];
    const float* W2   = (const float*)d_in[13];
    const float* al2  = (const float*)d_in[14];
    const float* ar2  = (const float*)d_in[15];
    float* out = (float*)d_out;

    const int E0 = in_sizes[1];
    const int E1 = in_sizes[3];
    const int E2 = in_sizes[5];

    float *hbuf, *obuf, *el, *er;
    int* rp;
    cudaGetSymbolAddress((void**)&hbuf, g_hbuf);
    cudaGetSymbolAddress((void**)&obuf, g_obuf);
    cudaGetSymbolAddress((void**)&el,   g_el);
    cudaGetSymbolAddress((void**)&er,   g_er);
    cudaGetSymbolAddress((void**)&rp,   g_rowptr);

    // ---------------- Layer 0: 200000x256 @ 256x192 ----------------
    {
        dim3 grid(FMID / 64, ceil_div(NODES0, 128));
        gemm_tf32_kernel<<<grid, 256>>>(x, W0, hbuf, NODES0, FMID, FIN);

        int warps = NODES0 * NHEAD;
        elr_kernel<<<ceil_div(warps * 32, 256), 256>>>(hbuf, al0, ar0, el, er,
                                                       NODES0, NHEAD, DH);
        rowptr_kernel<<<ceil_div(NODES1 + 1, 256), 256>>>(dst0, E0, NODES1, rp);
        aggregate2_kernel<NHEAD, DH, 4, true><<<NODES1, 4 * (FMID / 4)>>>(
            hbuf, el, er, src0, rp, obuf);
    }

    // ---------------- Layer 1: 100000x192 @ 192x192 ----------------
    {
        dim3 grid(FMID / 64, ceil_div(NODES1, 128));
        gemm_tf32_kernel<<<grid, 256>>>(obuf, W1, hbuf, NODES1, FMID, FMID);

        int warps = NODES1 * NHEAD;
        elr_kernel<<<ceil_div(warps * 32, 256), 256>>>(hbuf, al1, ar1, el, er,
                                                       NODES1, NHEAD, DH);
        rowptr_kernel<<<ceil_div(NODES2 + 1, 256), 256>>>(dst1, E1, NODES2, rp);
        aggregate2_kernel<NHEAD, DH, 4, true><<<NODES2, 4 * (FMID / 4)>>>(
            hbuf, el, er, src1, rp, obuf);
    }

    // ---------------- Layer 2: 50000x192 @ 192x40 (H=1, D=40) ----------------
    {
        dim3 grid(ceil_div(COUT, 64), ceil_div(NODES2, 128));
        sgemm_kernel<<<grid, 256>>>(obuf, W2, hbuf, NODES2, COUT, FMID);

        int warps = NODES2 * 1;
        elr_kernel<<<ceil_div(warps * 32, 256), 256>>>(hbuf, al2, ar2, el, er,
                                                       NODES2, 1, COUT);
        rowptr_kernel<<<ceil_div(NODES3 + 1, 256), 256>>>(dst2, E2, NODES3, rp);
        aggregate2_kernel<1, COUT, 8, false><<<NODES3, 8 * (COUT / 4)>>>(
            hbuf, el, er, src2, rp, out);
    }
}

// round 5
// speedup vs baseline: 1.5414x; 1.2231x over previous
#include <cuda_runtime.h>
#include <cstdint>
#include <mma.h>
#include <math.h>

using namespace nvcuda;

// ---------------------------------------------------------------------------
// Problem constants
// ---------------------------------------------------------------------------
#define NODES0 200000
#define NODES1 100000
#define NODES2 50000
#define NODES3 25000
#define FIN    256
#define DH     64
#define NHEAD  3
#define COUT   40
#define FMID   (NHEAD * DH)   // 192
#define COUT_PAD 48           // layer-2 GEMM output stride (16-col aligned)

// ---------------------------------------------------------------------------
// Static device scratch
// ---------------------------------------------------------------------------
__device__ __align__(128) float g_hbuf[(size_t)NODES0 * FMID];
__device__ __align__(128) float g_obuf[(size_t)NODES1 * FMID];
__device__ __align__(128) float g_el[(size_t)NODES0 * NHEAD];
__device__ __align__(128) float g_er[(size_t)NODES0 * NHEAD];
__device__ int g_rowptr[NODES1 + 1];

// ---------------------------------------------------------------------------
// cp.async helpers
// ---------------------------------------------------------------------------
__device__ __forceinline__ unsigned int smem_u32(const void* p) {
    return (unsigned int)__cvta_generic_to_shared(p);
}
__device__ __forceinline__ void cp16(unsigned int d, const void* s) {
    asm volatile("cp.async.cg.shared.global [%0], [%1], 16;" :: "r"(d), "l"(s));
}
#define CP_COMMIT() asm volatile("cp.async.commit_group;")
#define CP_WAIT1()  asm volatile("cp.async.wait_group 1;")

// ---------------------------------------------------------------------------
// TF32 wmma GEMM, 3-stage cp.async pipeline.
// IMPORTANT: fragments are rounded to tf32 with RN (__float_to_tf32) after
// the smem load — cp.async delivers raw fp32 and the MMA would otherwise
// TRUNCATE mantissas (biased error that compounds across layers).
// ---------------------------------------------------------------------------
__global__ __launch_bounds__(256) void gemm_tf32_pipe(
    const float* __restrict__ A, const float* __restrict__ B,
    float* __restrict__ C, int M, int N, int K, int ldc)
{
    constexpr int BM = 128, BN = 64, BK = 16;
    constexpr int LDA = BK + 4;   // 20
    constexpr int LDB = BN + 4;   // 68

    __shared__ float As[3][BM * LDA];
    __shared__ float Bs[3][BK * LDB];

    const int tid  = threadIdx.x;
    const int warp = tid >> 5;
    const int wm   = warp >> 1;
    const int wn   = warp & 1;
    const int brow = blockIdx.y * BM;
    const int bcol = blockIdx.x * BN;
    const int T    = K / BK;

    wmma::fragment<wmma::accumulator, 16, 16, 8, float> acc[2][2];
#pragma unroll
    for (int i = 0; i < 2; i++)
#pragma unroll
        for (int j = 0; j < 2; j++) wmma::fill_fragment(acc[i][j], 0.0f);

    const int br  = tid >> 4;      // B row 0..15
    const int bc4 = tid & 15;      // B float4 col 0..15
    int bgcol = bcol + bc4 * 4;
    if (bgcol + 4 > N) bgcol = N - 4;   // clamp (N%4==0); garbage only lands
                                        // in padded output cols, never read

#define PREFETCH(t, st)                                                        \
    do {                                                                       \
        int k0 = (t) * BK;                                                     \
        _Pragma("unroll")                                                      \
        for (int i = 0; i < 2; i++) {                                          \
            int idx = tid + i * 256;                                           \
            int r   = idx >> 2;                                                \
            int c4  = idx & 3;                                                 \
            int grow = brow + r;                                               \
            if (grow >= M) grow = M - 1;                                       \
            cp16(smem_u32(&As[st][r * LDA + c4 * 4]),                          \
                 &A[(size_t)grow * K + k0 + c4 * 4]);                          \
        }                                                                      \
        cp16(smem_u32(&Bs[st][br * LDB + bc4 * 4]),                            \
             &B[(size_t)(k0 + br) * N + bgcol]);                               \
        CP_COMMIT();                                                           \
    } while (0)

    PREFETCH(0, 0);
    PREFETCH(1, 1);

    for (int t = 0; t < T; t++) {
        CP_WAIT1();
        __syncthreads();
        if (t + 2 < T) {
            int st2 = (t + 2) % 3;
            PREFETCH(t + 2, st2);
        } else {
            CP_COMMIT();
        }
        const int st = t % 3;
#pragma unroll
        for (int kk = 0; kk < BK; kk += 8) {
            wmma::fragment<wmma::matrix_a, 16, 16, 8, wmma::precision::tf32, wmma::row_major> a[2];
            wmma::fragment<wmma::matrix_b, 16, 16, 8, wmma::precision::tf32, wmma::row_major> b[2];
#pragma unroll
            for (int i = 0; i < 2; i++) {
                wmma::load_matrix_sync(a[i], &As[st][(wm * 32 + i * 16) * LDA + kk], LDA);
#pragma unroll
                for (int e = 0; e < a[i].num_elements; e++)
                    a[i].x[e] = wmma::__float_to_tf32(a[i].x[e]);
            }
#pragma unroll
            for (int j = 0; j < 2; j++) {
                wmma::load_matrix_sync(b[j], &Bs[st][kk * LDB + wn * 32 + j * 16], LDB);
#pragma unroll
                for (int e = 0; e < b[j].num_elements; e++)
                    b[j].x[e] = wmma::__float_to_tf32(b[j].x[e]);
            }
#pragma unroll
            for (int i = 0; i < 2; i++)
#pragma unroll
                for (int j = 0; j < 2; j++)
                    wmma::mma_sync(acc[i][j], a[i], b[j], acc[i][j]);
        }
    }
#undef PREFETCH

#pragma unroll
    for (int i = 0; i < 2; i++) {
        int row0 = brow + wm * 32 + i * 16;
        if (row0 + 16 > M) continue;
#pragma unroll
        for (int j = 0; j < 2; j++) {
            int col0 = bcol + wn * 32 + j * 16;
            if (col0 + 16 > ldc) continue;
            wmma::store_matrix_sync(&C[(size_t)row0 * ldc + col0], acc[i][j], ldc,
                                    wmma::mem_row_major);
        }
    }
}

// ---------------------------------------------------------------------------
// Per-node attention logits (stride-aware).
// ---------------------------------------------------------------------------
__global__ void elr_kernel(const float* __restrict__ h,
                           const float* __restrict__ al,
                           const float* __restrict__ ar,
                           float* __restrict__ el, float* __restrict__ er,
                           int Nn, int H, int D, int stride)
{
    int gw   = (blockIdx.x * blockDim.x + threadIdx.x) >> 5;
    int lane = threadIdx.x & 31;
    if (gw >= Nn * H) return;
    int n = gw / H, head = gw % H;
    const float* hp  = h  + (size_t)n * stride + head * D;
    const float* alp = al + head * D;
    const float* arp = ar + head * D;
    float sl = 0.f, sr = 0.f;
    for (int d = lane; d < D; d += 32) {
        float v = hp[d];
        sl = fmaf(v, alp[d], sl);
        sr = fmaf(v, arp[d], sr);
    }
#pragma unroll
    for (int o = 16; o; o >>= 1) {
        sl += __shfl_xor_sync(0xffffffffu, sl, o);
        sr += __shfl_xor_sync(0xffffffffu, sr, o);
    }
    if (lane == 0) {
        el[n * H + head] = sl;
        er[n * H + head] = sr;
    }
}

// ---------------------------------------------------------------------------
// row_ptr from sorted dst.
// ---------------------------------------------------------------------------
__global__ void rowptr_kernel(const int* __restrict__ dst, int E, int n_dst,
                              int* __restrict__ rp)
{
    int d = blockIdx.x * blockDim.x + threadIdx.x;
    if (d > n_dst) return;
    int lo = 0, hi = E;
    while (lo < hi) {
        int mid = (lo + hi) >> 1;
        if (dst[mid] < d) lo = mid + 1; else hi = mid;
    }
    rp[d] = lo;
}

// ---------------------------------------------------------------------------
// Aggregate v3b: ONE WARP PER DST NODE, exact reference math (max-shifted
// softmax). First-chunk logits cached in registers, so nodes with degree<=32
// (the vast majority; avg ~10) pay no extra memory passes for the max.
// ---------------------------------------------------------------------------
__device__ __forceinline__ float leaky02(float v) {
    return v > 0.f ? v : 0.2f * v;
}

template <int H, int D, int STRIDE, bool RELU>
__global__ void agg3_kernel(const float* __restrict__ h,
                            const float* __restrict__ el,
                            const float* __restrict__ er,
                            const int* __restrict__ src,
                            const int* __restrict__ rp,
                            float* __restrict__ out, int n_dst)
{
    constexpr int HD  = H * D;
    constexpr int HD4 = HD / 4;
    constexpr int S4  = STRIDE / 4;
    constexpr int NJ  = (S4 + 31) / 32;

    const int gw = (blockIdx.x * blockDim.x + threadIdx.x) >> 5;
    if (gw >= n_dst) return;
    const int lane = threadIdx.x & 31;
    const int d = gw;
    const int start = rp[d];
    const int end   = rp[d + 1];

    float er_d[H];
#pragma unroll
    for (int hh = 0; hh < H; hh++) er_d[hh] = er[d * H + hh];

    // ---- Pass A: per-head max (first-chunk logits cached in v0) ----
    float v0[H], m[H];
#pragma unroll
    for (int hh = 0; hh < H; hh++) { v0[hh] = 0.f; m[hh] = -INFINITY; }
    int sn0 = 0;
    {
        int e = start + lane;
        if (e < end) {
            sn0 = src[e];
#pragma unroll
            for (int hh = 0; hh < H; hh++) {
                v0[hh] = leaky02(el[sn0 * H + hh] + er_d[hh]);
                m[hh]  = v0[hh];
            }
        }
    }
    for (int e = start + 32 + lane; e < end; e += 32) {
        int sn = src[e];
#pragma unroll
        for (int hh = 0; hh < H; hh++)
            m[hh] = fmaxf(m[hh], leaky02(el[sn * H + hh] + er_d[hh]));
    }
#pragma unroll
    for (int hh = 0; hh < H; hh++) {
#pragma unroll
        for (int o = 16; o; o >>= 1)
            m[hh] = fmaxf(m[hh], __shfl_xor_sync(0xffffffffu, m[hh], o));
    }

    // ---- Pass B: per-head sum of exp(v - m) ----
    float w0[H], s[H];
#pragma unroll
    for (int hh = 0; hh < H; hh++) { s[hh] = 0.f; w0[hh] = 0.f; }
    if (start + lane < end) {
#pragma unroll
        for (int hh = 0; hh < H; hh++) {
            w0[hh] = __expf(v0[hh] - m[hh]);
            s[hh]  = w0[hh];
        }
    }
    for (int e = start + 32 + lane; e < end; e += 32) {
        int sn = src[e];
#pragma unroll
        for (int hh = 0; hh < H; hh++)
            s[hh] += __expf(leaky02(el[sn * H + hh] + er_d[hh]) - m[hh]);
    }
#pragma unroll
    for (int hh = 0; hh < H; hh++) {
#pragma unroll
        for (int o = 16; o; o >>= 1)
            s[hh] += __shfl_xor_sync(0xffffffffu, s[hh], o);
    }
    float inv[H];
#pragma unroll
    for (int hh = 0; hh < H; hh++)
        inv[hh] = (s[hh] > 0.f) ? 1.0f / s[hh] : 0.f;

    // ---- Pass C: broadcast (src, alpha), accumulate float4 features ----
    int headj[NJ];
#pragma unroll
    for (int jj = 0; jj < NJ; jj++) {
        int j = lane + jj * 32;
        int hh = (j * 4) / D;
        headj[jj] = hh < H ? hh : H - 1;
    }

    float4 facc[NJ];
#pragma unroll
    for (int jj = 0; jj < NJ; jj++) facc[jj] = make_float4(0.f, 0.f, 0.f, 0.f);

    for (int e0 = start; e0 < end; e0 += 32) {
        const int cnt = min(32, end - e0);
        int sn_l = 0;
        float a_l[H];
#pragma unroll
        for (int hh = 0; hh < H; hh++) a_l[hh] = 0.f;
        if (e0 == start) {
            sn_l = sn0;
#pragma unroll
            for (int hh = 0; hh < H; hh++) a_l[hh] = w0[hh] * inv[hh];
        } else if (lane < cnt) {
            sn_l = src[e0 + lane];
#pragma unroll
            for (int hh = 0; hh < H; hh++)
                a_l[hh] = __expf(leaky02(el[sn_l * H + hh] + er_d[hh]) - m[hh]) * inv[hh];
        }
        for (int i = 0; i < cnt; i++) {
            const int sn = __shfl_sync(0xffffffffu, sn_l, i);
            float av[H];
#pragma unroll
            for (int hh = 0; hh < H; hh++)
                av[hh] = __shfl_sync(0xffffffffu, a_l[hh], i);
            const float4* hp = (const float4*)(h + (size_t)sn * STRIDE);
#pragma unroll
            for (int jj = 0; jj < NJ; jj++) {
                int j = lane + jj * 32;
                if (j < HD4) {
                    float4 v = hp[j];
                    float a  = av[headj[jj]];
                    facc[jj].x = fmaf(v.x, a, facc[jj].x);
                    facc[jj].y = fmaf(v.y, a, facc[jj].y);
                    facc[jj].z = fmaf(v.z, a, facc[jj].z);
                    facc[jj].w = fmaf(v.w, a, facc[jj].w);
                }
            }
        }
    }

#pragma unroll
    for (int jj = 0; jj < NJ; jj++) {
        int j = lane + jj * 32;
        if (j < HD4) {
            float4 r = facc[jj];
            if (RELU) {
                r.x = fmaxf(r.x, 0.f); r.y = fmaxf(r.y, 0.f);
                r.z = fmaxf(r.z, 0.f); r.w = fmaxf(r.w, 0.f);
            }
            ((float4*)(out + (size_t)d * HD))[j] = r;
        }
    }
}

// ---------------------------------------------------------------------------
// Launch
// ---------------------------------------------------------------------------
static inline int ceil_div(int a, int b) { return (a + b - 1) / b; }

extern "C" void kernel_launch(void* const* d_in, const int* in_sizes, int n_in,
                              void* d_out, int out_size)
{
    const float* x    = (const float*)d_in[0];
    const int*   src0 = (const int*)  d_in[1];
    const int*   dst0 = (const int*)  d_in[2];
    const int*   src1 = (const int*)  d_in[3];
    const int*   dst1 = (const int*)  d_in[4];
    const int*   src2 = (const int*)  d_in[5];
    const int*   dst2 = (const int*)  d_in[6];
    const float* W0   = (const float*)d_in[7];
    const float* al0  = (const float*)d_in[8];
    const float* ar0  = (const float*)d_in[9];
    const float* W1   = (const float*)d_in[10];
    const float* al1  = (const float*)d_in[11];
    const float* ar1  = (const float*)d_in[12];
    const float* W2   = (const float*)d_in[13];
    const float* al2  = (const float*)d_in[14];
    const float* ar2  = (const float*)d_in[15];
    float* out = (float*)d_out;

    const int E0 = in_sizes[1];
    const int E1 = in_sizes[3];
    const int E2 = in_sizes[5];

    float *hbuf, *obuf, *el, *er;
    int* rp;
    cudaGetSymbolAddress((void**)&hbuf, g_hbuf);
    cudaGetSymbolAddress((void**)&obuf, g_obuf);
    cudaGetSymbolAddress((void**)&el,   g_el);
    cudaGetSymbolAddress((void**)&er,   g_er);
    cudaGetSymbolAddress((void**)&rp,   g_rowptr);

    // ---------------- Layer 0: 200000x256 @ 256x192 ----------------
    {
        dim3 grid(FMID / 64, ceil_div(NODES0, 128));
        gemm_tf32_pipe<<<grid, 256>>>(x, W0, hbuf, NODES0, FMID, FIN, FMID);

        int warps = NODES0 * NHEAD;
        elr_kernel<<<ceil_div(warps * 32, 256), 256>>>(hbuf, al0, ar0, el, er,
                                                       NODES0, NHEAD, DH, FMID);
        rowptr_kernel<<<ceil_div(NODES1 + 1, 256), 256>>>(dst0, E0, NODES1, rp);
        agg3_kernel<NHEAD, DH, FMID, true><<<ceil_div(NODES1, 8), 256>>>(
            hbuf, el, er, src0, rp, obuf, NODES1);
    }

    // ---------------- Layer 1: 100000x192 @ 192x192 ----------------
    {
        dim3 grid(FMID / 64, ceil_div(NODES1, 128));
        gemm_tf32_pipe<<<grid, 256>>>(obuf, W1, hbuf, NODES1, FMID, FMID, FMID);

        int warps = NODES1 * NHEAD;
        elr_kernel<<<ceil_div(warps * 32, 256), 256>>>(hbuf, al1, ar1, el, er,
                                                       NODES1, NHEAD, DH, FMID);
        rowptr_kernel<<<ceil_div(NODES2 + 1, 256), 256>>>(dst1, E1, NODES2, rp);
        agg3_kernel<NHEAD, DH, FMID, true><<<ceil_div(NODES2, 8), 256>>>(
            hbuf, el, er, src1, rp, obuf, NODES2);
    }

    // ---------------- Layer 2: 50000x192 @ 192x40 (padded ldc=48) -------
    {
        dim3 grid(1, ceil_div(NODES2, 128));
        gemm_tf32_pipe<<<grid, 256>>>(obuf, W2, hbuf, NODES2, COUT, FMID, COUT_PAD);

        int warps = NODES2 * 1;
        elr_kernel<<<ceil_div(warps * 32, 256), 256>>>(hbuf, al2, ar2, el, er,
                                                       NODES2, 1, COUT, COUT_PAD);
        rowptr_kernel<<<ceil_div(NODES3 + 1, 256), 256>>>(dst2, E2, NODES3, rp);
        agg3_kernel<1, COUT, COUT_PAD, false><<<ceil_div(NODES3, 8), 256>>>(
            hbuf, el, er, src2, rp, out, NODES3);
    }
}

// round 6
// speedup vs baseline: 1.6383x; 1.0629x over previous
#include <cuda_runtime.h>
#include <cstdint>
#include <mma.h>
#include <math.h>

using namespace nvcuda;

// ---------------------------------------------------------------------------
// Problem constants
// ---------------------------------------------------------------------------
#define NODES0 200000
#define NODES1 100000
#define NODES2 50000
#define NODES3 25000
#define FIN    256
#define DH     64
#define NHEAD  3
#define COUT   40
#define FMID   (NHEAD * DH)   // 192
#define COUT_PAD 48
#define EDGE_MAX 1000000

// ---------------------------------------------------------------------------
// Static device scratch
// ---------------------------------------------------------------------------
__device__ __align__(128) float g_hbuf[(size_t)NODES0 * FMID];
__device__ __align__(128) float g_obuf[(size_t)NODES1 * FMID];
__device__ __align__(128) float g_el[(size_t)NODES0 * NHEAD];
__device__ __align__(128) float g_er[(size_t)NODES0 * NHEAD];
__device__ __align__(128) float g_alpha[(size_t)EDGE_MAX * NHEAD];
__device__ __align__(128) float g_W0r[FIN * FMID];
__device__ __align__(128) float g_W1r[FMID * FMID];
__device__ __align__(128) float g_W2r[FMID * COUT];
__device__ int g_rowptr[NODES1 + 1];

// ---------------------------------------------------------------------------
// cp.async helpers
// ---------------------------------------------------------------------------
__device__ __forceinline__ unsigned int smem_u32(const void* p) {
    return (unsigned int)__cvta_generic_to_shared(p);
}
__device__ __forceinline__ void cp16(unsigned int d, const void* s) {
    asm volatile("cp.async.cg.shared.global [%0], [%1], 16;" :: "r"(d), "l"(s));
}
#define CP_COMMIT() asm volatile("cp.async.commit_group;")
#define CP_WAIT1()  asm volatile("cp.async.wait_group 1;")

// ---------------------------------------------------------------------------
// Pre-round weight matrices to tf32-representable fp32 (RN), once per call.
// ---------------------------------------------------------------------------
__global__ void round_w_kernel(const float* __restrict__ W0,
                               const float* __restrict__ W1,
                               const float* __restrict__ W2,
                               float* __restrict__ W0r,
                               float* __restrict__ W1r,
                               float* __restrict__ W2r)
{
    int i = blockIdx.x * blockDim.x + threadIdx.x;
    if (i < FIN * FMID)  W0r[i] = wmma::__float_to_tf32(W0[i]);
    if (i < FMID * FMID) W1r[i] = wmma::__float_to_tf32(W1[i]);
    if (i < FMID * COUT) W2r[i] = wmma::__float_to_tf32(W2[i]);
}

// ---------------------------------------------------------------------------
// TF32 wmma GEMM, 3-stage cp.async pipeline.
// CONVA: round A fragments to tf32 (needed only when A isn't pre-rounded).
// B is always pre-rounded (weights).
// ---------------------------------------------------------------------------
template <bool CONVA>
__global__ __launch_bounds__(256) void gemm_tf32_pipe(
    const float* __restrict__ A, const float* __restrict__ B,
    float* __restrict__ C, int M, int N, int K, int ldc)
{
    constexpr int BM = 128, BN = 64, BK = 16;
    constexpr int LDA = BK + 4;   // 20
    constexpr int LDB = BN + 4;   // 68

    __shared__ float As[3][BM * LDA];
    __shared__ float Bs[3][BK * LDB];

    const int tid  = threadIdx.x;
    const int warp = tid >> 5;
    const int wm   = warp >> 1;
    const int wn   = warp & 1;
    const int brow = blockIdx.y * BM;
    const int bcol = blockIdx.x * BN;
    const int T    = K / BK;

    wmma::fragment<wmma::accumulator, 16, 16, 8, float> acc[2][2];
#pragma unroll
    for (int i = 0; i < 2; i++)
#pragma unroll
        for (int j = 0; j < 2; j++) wmma::fill_fragment(acc[i][j], 0.0f);

    const int br  = tid >> 4;
    const int bc4 = tid & 15;
    int bgcol = bcol + bc4 * 4;
    if (bgcol + 4 > N) bgcol = N - 4;   // clamp; garbage lands only in
                                        // padded output cols, never read

#define PREFETCH(t, st)                                                        \
    do {                                                                       \
        int k0 = (t) * BK;                                                     \
        _Pragma("unroll")                                                      \
        for (int i = 0; i < 2; i++) {                                          \
            int idx = tid + i * 256;                                           \
            int r   = idx >> 2;                                                \
            int c4  = idx & 3;                                                 \
            int grow = brow + r;                                               \
            if (grow >= M) grow = M - 1;                                       \
            cp16(smem_u32(&As[st][r * LDA + c4 * 4]),                          \
                 &A[(size_t)grow * K + k0 + c4 * 4]);                          \
        }                                                                      \
        cp16(smem_u32(&Bs[st][br * LDB + bc4 * 4]),                            \
             &B[(size_t)(k0 + br) * N + bgcol]);                               \
        CP_COMMIT();                                                           \
    } while (0)

    PREFETCH(0, 0);
    PREFETCH(1, 1);

    for (int t = 0; t < T; t++) {
        CP_WAIT1();
        __syncthreads();
        if (t + 2 < T) {
            int st2 = (t + 2) % 3;
            PREFETCH(t + 2, st2);
        } else {
            CP_COMMIT();
        }
        const int st = t % 3;
#pragma unroll
        for (int kk = 0; kk < BK; kk += 8) {
            wmma::fragment<wmma::matrix_a, 16, 16, 8, wmma::precision::tf32, wmma::row_major> a[2];
            wmma::fragment<wmma::matrix_b, 16, 16, 8, wmma::precision::tf32, wmma::row_major> b[2];
#pragma unroll
            for (int i = 0; i < 2; i++) {
                wmma::load_matrix_sync(a[i], &As[st][(wm * 32 + i * 16) * LDA + kk], LDA);
                if (CONVA) {
#pragma unroll
                    for (int e = 0; e < a[i].num_elements; e++)
                        a[i].x[e] = wmma::__float_to_tf32(a[i].x[e]);
                }
            }
#pragma unroll
            for (int j = 0; j < 2; j++)
                wmma::load_matrix_sync(b[j], &Bs[st][kk * LDB + wn * 32 + j * 16], LDB);
#pragma unroll
            for (int i = 0; i < 2; i++)
#pragma unroll
                for (int j = 0; j < 2; j++)
                    wmma::mma_sync(acc[i][j], a[i], b[j], acc[i][j]);
        }
    }
#undef PREFETCH

#pragma unroll
    for (int i = 0; i < 2; i++) {
        int row0 = brow + wm * 32 + i * 16;
        if (row0 + 16 > M) continue;
#pragma unroll
        for (int j = 0; j < 2; j++) {
            int col0 = bcol + wn * 32 + j * 16;
            if (col0 + 16 > ldc) continue;
            wmma::store_matrix_sync(&C[(size_t)row0 * ldc + col0], acc[i][j], ldc,
                                    wmma::mem_row_major);
        }
    }
}

// ---------------------------------------------------------------------------
// Per-node attention logits (stride-aware).
// ---------------------------------------------------------------------------
__global__ void elr_kernel(const float* __restrict__ h,
                           const float* __restrict__ al,
                           const float* __restrict__ ar,
                           float* __restrict__ el, float* __restrict__ er,
                           int Nn, int H, int D, int stride)
{
    int gw   = (blockIdx.x * blockDim.x + threadIdx.x) >> 5;
    int lane = threadIdx.x & 31;
    if (gw >= Nn * H) return;
    int n = gw / H, head = gw % H;
    const float* hp  = h  + (size_t)n * stride + head * D;
    const float* alp = al + head * D;
    const float* arp = ar + head * D;
    float sl = 0.f, sr = 0.f;
    for (int d = lane; d < D; d += 32) {
        float v = hp[d];
        sl = fmaf(v, alp[d], sl);
        sr = fmaf(v, arp[d], sr);
    }
#pragma unroll
    for (int o = 16; o; o >>= 1) {
        sl += __shfl_xor_sync(0xffffffffu, sl, o);
        sr += __shfl_xor_sync(0xffffffffu, sr, o);
    }
    if (lane == 0) {
        el[n * H + head] = sl;
        er[n * H + head] = sr;
    }
}

// ---------------------------------------------------------------------------
// row_ptr from sorted dst.
// ---------------------------------------------------------------------------
__global__ void rowptr_kernel(const int* __restrict__ dst, int E, int n_dst,
                              int* __restrict__ rp)
{
    int d = blockIdx.x * blockDim.x + threadIdx.x;
    if (d > n_dst) return;
    int lo = 0, hi = E;
    while (lo < hi) {
        int mid = (lo + hi) >> 1;
        if (dst[mid] < d) lo = mid + 1; else hi = mid;
    }
    rp[d] = lo;
}

// ---------------------------------------------------------------------------
// gat_softmax: warp per dst. Max-shifted softmax over incident edges;
// writes NORMALIZED alpha[e*H+h] to global. First-chunk logits cached in regs.
// ---------------------------------------------------------------------------
__device__ __forceinline__ float leaky02(float v) {
    return v > 0.f ? v : 0.2f * v;
}

template <int H>
__global__ __launch_bounds__(256) void gat_softmax(
    const float* __restrict__ el, const float* __restrict__ er,
    const int* __restrict__ src, const int* __restrict__ rp,
    float* __restrict__ alpha, int n_dst)
{
    const int gw = (blockIdx.x * blockDim.x + threadIdx.x) >> 5;
    if (gw >= n_dst) return;
    const int lane = threadIdx.x & 31;
    const int d = gw;
    const int start = rp[d];
    const int end   = rp[d + 1];

    float er_d[H];
#pragma unroll
    for (int hh = 0; hh < H; hh++) er_d[hh] = er[d * H + hh];

    // Pass A: max (first chunk cached in v0)
    float v0[H], m[H];
#pragma unroll
    for (int hh = 0; hh < H; hh++) { v0[hh] = 0.f; m[hh] = -INFINITY; }
    {
        int e = start + lane;
        if (e < end) {
            int sn = src[e];
#pragma unroll
            for (int hh = 0; hh < H; hh++) {
                v0[hh] = leaky02(el[sn * H + hh] + er_d[hh]);
                m[hh]  = v0[hh];
            }
        }
    }
    for (int e = start + 32 + lane; e < end; e += 32) {
        int sn = src[e];
#pragma unroll
        for (int hh = 0; hh < H; hh++)
            m[hh] = fmaxf(m[hh], leaky02(el[sn * H + hh] + er_d[hh]));
    }
#pragma unroll
    for (int hh = 0; hh < H; hh++)
#pragma unroll
        for (int o = 16; o; o >>= 1)
            m[hh] = fmaxf(m[hh], __shfl_xor_sync(0xffffffffu, m[hh], o));

    // Pass B: sum of exp(v-m)
    float w0[H], s[H];
#pragma unroll
    for (int hh = 0; hh < H; hh++) { s[hh] = 0.f; w0[hh] = 0.f; }
    if (start + lane < end) {
#pragma unroll
        for (int hh = 0; hh < H; hh++) {
            w0[hh] = __expf(v0[hh] - m[hh]);
            s[hh]  = w0[hh];
        }
    }
    for (int e = start + 32 + lane; e < end; e += 32) {
        int sn = src[e];
#pragma unroll
        for (int hh = 0; hh < H; hh++)
            s[hh] += __expf(leaky02(el[sn * H + hh] + er_d[hh]) - m[hh]);
    }
#pragma unroll
    for (int hh = 0; hh < H; hh++)
#pragma unroll
        for (int o = 16; o; o >>= 1)
            s[hh] += __shfl_xor_sync(0xffffffffu, s[hh], o);
    float inv[H];
#pragma unroll
    for (int hh = 0; hh < H; hh++)
        inv[hh] = (s[hh] > 0.f) ? 1.0f / s[hh] : 0.f;

    // Pass C: write normalized alphas
    if (start + lane < end) {
        int e = start + lane;
#pragma unroll
        for (int hh = 0; hh < H; hh++)
            alpha[(size_t)e * H + hh] = w0[hh] * inv[hh];
    }
    for (int e = start + 32 + lane; e < end; e += 32) {
        int sn = src[e];
#pragma unroll
        for (int hh = 0; hh < H; hh++)
            alpha[(size_t)e * H + hh] =
                __expf(leaky02(el[sn * H + hh] + er_d[hh]) - m[hh]) * inv[hh];
    }
}

// ---------------------------------------------------------------------------
// gat_gather: warp per dst. Pure weighted feature gather using precomputed
// alpha. No exp, no shfl. Unrolled by 2 edges for MLP.
// TF32OUT: round output to tf32-representable (it feeds the next GEMM as A).
// ---------------------------------------------------------------------------
template <int H, int D, int STRIDE, bool RELU, bool TF32OUT>
__global__ __launch_bounds__(256) void gat_gather(
    const float* __restrict__ h, const float* __restrict__ alpha,
    const int* __restrict__ src, const int* __restrict__ rp,
    float* __restrict__ out, int n_dst)
{
    constexpr int HD  = H * D;
    constexpr int HD4 = HD / 4;
    constexpr int NJ  = (HD4 + 31) / 32;

    const int gw = (blockIdx.x * blockDim.x + threadIdx.x) >> 5;
    if (gw >= n_dst) return;
    const int lane = threadIdx.x & 31;
    const int d = gw;
    const int start = rp[d];
    const int end   = rp[d + 1];

    int headj[NJ];
#pragma unroll
    for (int jj = 0; jj < NJ; jj++) {
        int j = lane + jj * 32;
        int hh = (j * 4) / D;
        headj[jj] = hh < H ? hh : H - 1;
    }

    float4 facc[NJ];
#pragma unroll
    for (int jj = 0; jj < NJ; jj++) facc[jj] = make_float4(0.f, 0.f, 0.f, 0.f);

    int e = start;
    for (; e + 2 <= end; e += 2) {
        const int sn0 = __ldg(&src[e]);
        const int sn1 = __ldg(&src[e + 1]);
        float a0[NJ], a1[NJ];
#pragma unroll
        for (int jj = 0; jj < NJ; jj++) {
            a0[jj] = __ldg(&alpha[(size_t)e * H + headj[jj]]);
            a1[jj] = __ldg(&alpha[(size_t)(e + 1) * H + headj[jj]]);
        }
        const float4* hp0 = (const float4*)(h + (size_t)sn0 * STRIDE);
        const float4* hp1 = (const float4*)(h + (size_t)sn1 * STRIDE);
#pragma unroll
        for (int jj = 0; jj < NJ; jj++) {
            int j = lane + jj * 32;
            if (j < HD4) {
                float4 v0 = hp0[j];
                float4 v1 = hp1[j];
                facc[jj].x = fmaf(v0.x, a0[jj], facc[jj].x);
                facc[jj].y = fmaf(v0.y, a0[jj], facc[jj].y);
                facc[jj].z = fmaf(v0.z, a0[jj], facc[jj].z);
                facc[jj].w = fmaf(v0.w, a0[jj], facc[jj].w);
                facc[jj].x = fmaf(v1.x, a1[jj], facc[jj].x);
                facc[jj].y = fmaf(v1.y, a1[jj], facc[jj].y);
                facc[jj].z = fmaf(v1.z, a1[jj], facc[jj].z);
                facc[jj].w = fmaf(v1.w, a1[jj], facc[jj].w);
            }
        }
    }
    if (e < end) {
        const int sn0 = __ldg(&src[e]);
        const float4* hp0 = (const float4*)(h + (size_t)sn0 * STRIDE);
#pragma unroll
        for (int jj = 0; jj < NJ; jj++) {
            int j = lane + jj * 32;
            if (j < HD4) {
                float a = __ldg(&alpha[(size_t)e * H + headj[jj]]);
                float4 v = hp0[j];
                facc[jj].x = fmaf(v.x, a, facc[jj].x);
                facc[jj].y = fmaf(v.y, a, facc[jj].y);
                facc[jj].z = fmaf(v.z, a, facc[jj].z);
                facc[jj].w = fmaf(v.w, a, facc[jj].w);
            }
        }
    }

#pragma unroll
    for (int jj = 0; jj < NJ; jj++) {
        int j = lane + jj * 32;
        if (j < HD4) {
            float4 r = facc[jj];
            if (RELU) {
                r.x = fmaxf(r.x, 0.f); r.y = fmaxf(r.y, 0.f);
                r.z = fmaxf(r.z, 0.f); r.w = fmaxf(r.w, 0.f);
            }
            if (TF32OUT) {
                r.x = wmma::__float_to_tf32(r.x);
                r.y = wmma::__float_to_tf32(r.y);
                r.z = wmma::__float_to_tf32(r.z);
                r.w = wmma::__float_to_tf32(r.w);
            }
            ((float4*)(out + (size_t)d * HD))[j] = r;
        }
    }
}

// ---------------------------------------------------------------------------
// Launch
// ---------------------------------------------------------------------------
static inline int ceil_div(int a, int b) { return (a + b - 1) / b; }

extern "C" void kernel_launch(void* const* d_in, const int* in_sizes, int n_in,
                              void* d_out, int out_size)
{
    const float* x    = (const float*)d_in[0];
    const int*   src0 = (const int*)  d_in[1];
    const int*   dst0 = (const int*)  d_in[2];
    const int*   src1 = (const int*)  d_in[3];
    const int*   dst1 = (const int*)  d_in[4];
    const int*   src2 = (const int*)  d_in[5];
    const int*   dst2 = (const int*)  d_in[6];
    const float* W0   = (const float*)d_in[7];
    const float* al0  = (const float*)d_in[8];
    const float* ar0  = (const float*)d_in[9];
    const float* W1   = (const float*)d_in[10];
    const float* al1  = (const float*)d_in[11];
    const float* ar1  = (const float*)d_in[12];
    const float* W2   = (const float*)d_in[13];
    const float* al2  = (const float*)d_in[14];
    const float* ar2  = (const float*)d_in[15];
    float* out = (float*)d_out;

    const int E0 = in_sizes[1];
    const int E1 = in_sizes[3];
    const int E2 = in_sizes[5];

    float *hbuf, *obuf, *el, *er, *alpha, *w0r, *w1r, *w2r;
    int* rp;
    cudaGetSymbolAddress((void**)&hbuf,  g_hbuf);
    cudaGetSymbolAddress((void**)&obuf,  g_obuf);
    cudaGetSymbolAddress((void**)&el,    g_el);
    cudaGetSymbolAddress((void**)&er,    g_er);
    cudaGetSymbolAddress((void**)&alpha, g_alpha);
    cudaGetSymbolAddress((void**)&w0r,   g_W0r);
    cudaGetSymbolAddress((void**)&w1r,   g_W1r);
    cudaGetSymbolAddress((void**)&w2r,   g_W2r);
    cudaGetSymbolAddress((void**)&rp,    g_rowptr);

    round_w_kernel<<<ceil_div(FIN * FMID, 256), 256>>>(W0, W1, W2, w0r, w1r, w2r);

    // ---------------- Layer 0: 200000x256 @ 256x192 ----------------
    {
        dim3 grid(FMID / 64, ceil_div(NODES0, 128));
        gemm_tf32_pipe<true><<<grid, 256>>>(x, w0r, hbuf, NODES0, FMID, FIN, FMID);

        int warps = NODES0 * NHEAD;
        elr_kernel<<<ceil_div(warps * 32, 256), 256>>>(hbuf, al0, ar0, el, er,
                                                       NODES0, NHEAD, DH, FMID);
        rowptr_kernel<<<ceil_div(NODES1 + 1, 256), 256>>>(dst0, E0, NODES1, rp);
        gat_softmax<NHEAD><<<ceil_div(NODES1, 8), 256>>>(el, er, src0, rp, alpha, NODES1);
        gat_gather<NHEAD, DH, FMID, true, true><<<ceil_div(NODES1, 8), 256>>>(
            hbuf, alpha, src0, rp, obuf, NODES1);
    }

    // ---------------- Layer 1: 100000x192 @ 192x192 ----------------
    {
        dim3 grid(FMID / 64, ceil_div(NODES1, 128));
        gemm_tf32_pipe<false><<<grid, 256>>>(obuf, w1r, hbuf, NODES1, FMID, FMID, FMID);

        int warps = NODES1 * NHEAD;
        elr_kernel<<<ceil_div(warps * 32, 256), 256>>>(hbuf, al1, ar1, el, er,
                                                       NODES1, NHEAD, DH, FMID);
        rowptr_kernel<<<ceil_div(NODES2 + 1, 256), 256>>>(dst1, E1, NODES2, rp);
        gat_softmax<NHEAD><<<ceil_div(NODES2, 8), 256>>>(el, er, src1, rp, alpha, NODES2);
        gat_gather<NHEAD, DH, FMID, true, true><<<ceil_div(NODES2, 8), 256>>>(
            hbuf, alpha, src1, rp, obuf, NODES2);
    }

    // ---------------- Layer 2: 50000x192 @ 192x40 (padded ldc=48) -------
    {
        dim3 grid(1, ceil_div(NODES2, 128));
        gemm_tf32_pipe<false><<<grid, 256>>>(obuf, w2r, hbuf, NODES2, COUT, FMID, COUT_PAD);

        int warps = NODES2 * 1;
        elr_kernel<<<ceil_div(warps * 32, 256), 256>>>(hbuf, al2, ar2, el, er,
                                                       NODES2, 1, COUT, COUT_PAD);
        rowptr_kernel<<<ceil_div(NODES3 + 1, 256), 256>>>(dst2, E2, NODES3, rp);
        gat_softmax<1><<<ceil_div(NODES3, 8), 256>>>(el, er, src2, rp, alpha, NODES3);
        gat_gather<1, COUT, COUT_PAD, false, false><<<ceil_div(NODES3, 8), 256>>>(
            hbuf, alpha, src2, rp, out, NODES3);
    }
}